// round 17
// baseline (speedup 1.0000x reference)
#include <cuda_runtime.h>
#include <math.h>

#define BB 32
#define AA 8732
#define CC 201
#define GG 50
#define TPB 256
#define APW 8                 // anchors per warp
#define MAXFG 1024
#define NBIN 1024
#define QS 64.0f              // bin width 1/64
#define FPS 4096.0f           // fixed-point sum scale
#define SUMMASK ((1ull << 40) - 1)
#define GRPF (APW * CC)       // 1608 floats per warp group
#define NIT 13                // ceil(1608 / 128)

// Scratch (no allocations). All state self-resets for graph replay.
__device__ unsigned long long g_hist[BB * NBIN];  // packed {count<<40 | fpsum}
__device__ float2   g_fg[BB * MAXFG];
__device__ int      g_row_nfg[BB];
__device__ int      g_row_done[BB];               // anchors completed per row
__device__ float4   g_row_out[BB];
__device__ int      g_done;

__device__ __forceinline__ int atom_add_release(int* p, int v) {
    int old;
    asm volatile("atom.release.gpu.global.add.s32 %0, [%1], %2;"
                 : "=r"(old) : "l"(p), "r"(v) : "memory");
    return old;
}

// ---------------------------------------------------------------------------
// Warp-collective per-row select: lane-strided histogram suffix scan, no
// barriers. Runs once per row by the warp that completes it; overlaps with
// other rows' streaming. __noinline__ to limit register coupling.
// ---------------------------------------------------------------------------
__device__ __noinline__ void select_row(int r,
                                        const float* __restrict__ rej,
                                        const int*   __restrict__ img_label,
                                        float*       __restrict__ out) {
    int lane = threadIdx.x & 31;
    __threadfence();                       // acquire (<=32 warps ever here)

    int nfg = __ldcg(&g_row_nfg[r]);
    float fgc = 0.f, bbs = 0.f;
    for (int i = lane; i < nfg; i += 32) {
        float2 d = __ldcg(&g_fg[r * MAXFG + i]);
        fgc += d.x;
        bbs += d.y;
    }
#pragma unroll
    for (int o = 16; o; o >>= 1) {
        fgc += __shfl_xor_sync(0xffffffffu, fgc, o);
        bbs += __shfl_xor_sync(0xffffffffu, bbs, o);
    }

    int k = 3 * nfg;
    float bg = 0.f;
    ulonglong2* hp = (ulonglong2*)(g_hist + r * NBIN) + lane * 16;  // 32 bins/lane

    if (k > 0) {
        int tc = 0; float tf = 0.f;
#pragma unroll
        for (int j = 0; j < 16; j++) {
            ulonglong2 pv = __ldcg(&hp[j]);
            tc += (int)(pv.x >> 40) + (int)(pv.y >> 40);
            tf += (float)(pv.x & SUMMASK) + (float)(pv.y & SUMMASK);
        }
        tf *= (1.0f / FPS);

        // Warp suffix scan (higher lane = higher bins).
        int sc = tc; float sf = tf;
#pragma unroll
        for (int o = 1; o < 32; o <<= 1) {
            int   t = __shfl_down_sync(0xffffffffu, sc, o);
            float g = __shfl_down_sync(0xffffffffu, sf, o);
            if (lane + o < 32) { sc += t; sf += g; }
        }
        int   cab = sc - tc;              // count strictly above my bins
        float fab = sf - tf;
        bool own = (cab < k) && (cab + tc >= k);

        int B = 0, cex = 0; float fex = 0.f;
        if (own) {                        // exactly one lane; walk high->low
            int run = cab; float fr = fab;
            bool found = false;
#pragma unroll
            for (int j = 15; j >= 0; --j) {
                ulonglong2 pv = __ldcg(&hp[j]);
                int   cy = (int)(pv.y >> 40);
                float fy = (float)(pv.y & SUMMASK) * (1.0f / FPS);
                if (!found && run + cy >= k) {
                    B = lane * 32 + 2 * j + 1; cex = run; fex = fr; found = true;
                }
                if (!found) { run += cy; fr += fy; }
                int   cx = (int)(pv.x >> 40);
                float fx = (float)(pv.x & SUMMASK) * (1.0f / FPS);
                if (!found && run + cx >= k) {
                    B = lane * 32 + 2 * j; cex = run; fex = fr; found = true;
                }
                if (!found) { run += cx; fr += fx; }
            }
        }
        unsigned mk = __ballot_sync(0xffffffffu, own);
        int src = mk ? (__ffs(mk) - 1) : 0;
        B   = __shfl_sync(0xffffffffu, B,   src);
        cex = __shfl_sync(0xffffffffu, cex, src);
        fex = __shfl_sync(0xffffffffu, fex, src);
        bg = fex + (float)(k - cex) * ((float)B * (1.0f / QS));
    }

    // Zero histogram for next graph replay (unconditional).
    ulonglong2 z2 = make_ulonglong2(0ull, 0ull);
#pragma unroll
    for (int j = 0; j < 16; j++) hp[j] = z2;

    int gl = 0;
    if (lane == 0) {
        g_row_out[r]  = make_float4(fgc, bg, bbs, (float)nfg);
        g_row_nfg[r]  = 0;
        g_row_done[r] = 0;
        gl = (atom_add_release(&g_done, 1) == BB - 1);
    }
    gl = __shfl_sync(0xffffffffu, gl, 0);
    if (!gl) return;

    // Globally-last warp: finalize (lane = batch row).
    __threadfence();
    float4 rr = __ldcg(&g_row_out[lane]);
    float l0 = rej[2 * lane], l1 = rej[2 * lane + 1];
    float mm = fmaxf(l0, l1);
    float lse = mm + __logf(__expf(l0 - mm) + __expf(l1 - mm));
    float vl = lse - (img_label[lane] == 0 ? l0 : l1);
    float fc = rr.x, bgs2 = rr.y, bx = rr.z, cn = rr.w;
#pragma unroll
    for (int o = 16; o; o >>= 1) {
        fc   += __shfl_xor_sync(0xffffffffu, fc,   o);
        bgs2 += __shfl_xor_sync(0xffffffffu, bgs2, o);
        bx   += __shfl_xor_sync(0xffffffffu, bx,   o);
        cn   += __shfl_xor_sync(0xffffffffu, cn,   o);
        vl   += __shfl_xor_sync(0xffffffffu, vl,   o);
    }
    if (lane == 0) {
        float N   = fmaxf(1.f, cn);
        float reg = bx / N;
        float cls = (fc + bgs2) / N;
        float v   = vl / (float)BB;
        out[0] = 0.5f * (reg + cls) + 0.5f * v;
        out[1] = reg;
        out[2] = cls;
        out[3] = v;
        g_done = 0;
    }
}

// ---------------------------------------------------------------------------
// Fused kernel: R16 streaming (8 anchors/warp, 13x LDG.128) with NO block
// barriers; warp-granular release accounting; row-last warp runs select.
// ---------------------------------------------------------------------------
__global__ void __launch_bounds__(TPB)
fused_kernel(const float* __restrict__ boxes,
             const int*   __restrict__ labels,
             const int*   __restrict__ img_label,
             const float* __restrict__ bbox_reg,
             const float* __restrict__ cls_logits,
             const float* __restrict__ rej,
             const float* __restrict__ anchors,
             const int*   __restrict__ matched,
             float*       __restrict__ out) {
    int tid  = threadIdx.x;
    int wid  = tid >> 5;
    int lane = tid & 31;
    int base = (blockIdx.x * (TPB / 32) + wid) * APW;     // first anchor of group
    const float4* lp4 = (const float4*)(cls_logits + (size_t)base * CC);

    // Batched vector loads (13 x LDG.128).
    float4 d[NIT];
#pragma unroll
    for (int it = 0; it < NIT; it++) {
        int e = it * 128 + lane * 4;
        if (e < GRPF)
            d[it] = __ldcs(lp4 + it * 32 + lane);
        else
            d[it] = make_float4(-1e30f, -1e30f, -1e30f, -1e30f);
    }

    float acc[APW];
#pragma unroll
    for (int i = 0; i < APW; i++) acc[i] = 0.f;
#pragma unroll
    for (int it = 0; it < NIT; it++) {
        const int A0  = (it * 128) / CC;
        const int BND = (A0 + 1) * CC;
        const bool SPLIT = (BND < it * 128 + 128) && (A0 + 1 < APW);
        float ex0 = __expf(d[it].x);
        float ex1 = __expf(d[it].y);
        float ex2 = __expf(d[it].z);
        float ex3 = __expf(d[it].w);
        int e = it * 128 + lane * 4;
        if (SPLIT) {
            acc[A0]                   += (e + 0 < BND) ? ex0 : 0.f;
            acc[(A0 + 1) & (APW - 1)] += (e + 0 < BND) ? 0.f : ex0;
            acc[A0]                   += (e + 1 < BND) ? ex1 : 0.f;
            acc[(A0 + 1) & (APW - 1)] += (e + 1 < BND) ? 0.f : ex1;
            acc[A0]                   += (e + 2 < BND) ? ex2 : 0.f;
            acc[(A0 + 1) & (APW - 1)] += (e + 2 < BND) ? 0.f : ex2;
            acc[A0]                   += (e + 3 < BND) ? ex3 : 0.f;
            acc[(A0 + 1) & (APW - 1)] += (e + 3 < BND) ? 0.f : ex3;
        } else {
            acc[A0] += ex0 + ex1 + ex2 + ex3;
        }
    }

#pragma unroll
    for (int o = 16; o; o >>= 1)
#pragma unroll
        for (int i = 0; i < APW; i++)
            acc[i] += __shfl_xor_sync(0xffffffffu, acc[i], o);

    if (lane < APW) {
        float ss = acc[0];
#pragma unroll
        for (int i = 1; i < APW; i++) if (lane == i) ss = acc[i];
        int  gw = base + lane;
        int  b  = gw / AA;
        int  m  = matched[gw];
        bool fg = (m >= 0);
        int  t  = fg ? labels[b * GG + m] : 0;
        float cls = __logf(ss) - cls_logits[(size_t)gw * CC + t];
        if (!fg) {
            float cc = fmaxf(cls, 0.f);
            int   q  = min((int)(cc * QS), NBIN - 1);
            unsigned long long pk =
                (1ull << 40) | (unsigned long long)(unsigned)(cc * FPS);
            atomicAdd(&g_hist[b * NBIN + q], pk);
        } else {
            const float* anc = anchors + (size_t)gw * 4;
            const float* gt  = boxes + ((size_t)b * GG + m) * 4;
            float a0 = anc[0], a1 = anc[1], a2 = anc[2], a3 = anc[3];
            float g0 = gt[0],  g1 = gt[1],  g2 = gt[2],  g3 = gt[3];
            float awd = a2 - a0, aht = a3 - a1;
            float acx = a0 + 0.5f * awd, acy = a1 + 0.5f * aht;
            float gwd = g2 - g0, ght = g3 - g1;
            float gcx = g0 + 0.5f * gwd, gcy = g1 + 0.5f * ght;
            float tt0 = 10.f * (gcx - acx) / awd;
            float tt1 = 10.f * (gcy - acy) / aht;
            float tt2 = 5.f * logf(gwd / awd);
            float tt3 = 5.f * logf(ght / aht);
            const float* r = bbox_reg + (size_t)gw * 4;
            float d0 = r[0] - tt0, d1 = r[1] - tt1;
            float d2 = r[2] - tt2, d3 = r[3] - tt3;
            float q0 = fabsf(d0), q1 = fabsf(d1);
            float q2 = fabsf(d2), q3 = fabsf(d3);
            float bbx;
            bbx  = (q0 < 1.f) ? 0.5f * d0 * d0 : (q0 - 0.5f);
            bbx += (q1 < 1.f) ? 0.5f * d1 * d1 : (q1 - 0.5f);
            bbx += (q2 < 1.f) ? 0.5f * d2 * d2 : (q2 - 0.5f);
            bbx += (q3 < 1.f) ? 0.5f * d3 * d3 : (q3 - 0.5f);
            int slot = atomicAdd(&g_row_nfg[b], 1);
            g_fg[b * MAXFG + slot] = make_float2(cls, bbx);
        }
    }

    // ---- warp-granular done accounting (NO __syncthreads anywhere) ----
    __syncwarp();                         // orders all lanes' stores
    int b0 = base / AA;
    int b1 = (base + APW - 1) / AA;       // straddles <= 2 rows
    int n0 = (b1 > b0) ? (b1 * AA - base) : APW;
    int last0 = 0, last1 = 0;
    if (lane == 0) {
        int old = atom_add_release(&g_row_done[b0], n0);
        last0 = (old + n0 == AA);
        if (b1 > b0) {
            int n1 = APW - n0;
            int old1 = atom_add_release(&g_row_done[b1], n1);
            last1 = (old1 + n1 == AA);
        }
    }
    last0 = __shfl_sync(0xffffffffu, last0, 0);
    last1 = __shfl_sync(0xffffffffu, last1, 0);
    if (last0) select_row(b0, rej, img_label, out);
    if (last1) select_row(b1, rej, img_label, out);
}

extern "C" void kernel_launch(void* const* d_in, const int* in_sizes, int n_in,
                              void* d_out, int out_size) {
    const float* boxes      = (const float*)d_in[0];
    const int*   labels     = (const int*)  d_in[1];
    const int*   image_lab  = (const int*)  d_in[2];
    const float* bbox_reg   = (const float*)d_in[3];
    const float* cls_logits = (const float*)d_in[4];
    const float* rej        = (const float*)d_in[5];
    const float* anchors    = (const float*)d_in[6];
    const int*   matched    = (const int*)  d_in[7];

    const int blocks = (BB * AA) / (APW * (TPB / 32));   // 4366 exact
    fused_kernel<<<blocks, TPB>>>(boxes, labels, image_lab, bbox_reg,
                                  cls_logits, rej, anchors, matched,
                                  (float*)d_out);
}